// round 1
// baseline (speedup 1.0000x reference)
#include <cuda_runtime.h>
#include <cuda_bf16.h>

#define N_VOX 150000
#define C_IN  32
#define C_OUT 64
#define NK    27
#define EPS   1e-5f

#define TILE_N  128
#define THREADS 256

// Scratch for cross-kernel reduction (no cudaMalloc allowed).
__device__ float g_sum[C_OUT];
__device__ float g_sq[C_OUT];
__device__ float g_scale[C_OUT];
__device__ float g_bias[C_OUT];

__global__ void zero_kernel() {
    int t = threadIdx.x;
    if (t < C_OUT) { g_sum[t] = 0.f; g_sq[t] = 0.f; }
}

// Fused gather + GEMM + partial batch-stats.
// Block: 256 threads computes TILE_N=128 voxels x 64 couts.
// Thread (tc = t&15 -> cout quad, tr = t>>4 -> voxel lane) owns an
// 8-voxel x 4-cout register microtile.
__global__ void __launch_bounds__(THREADS, 2)
conv_kernel(const float* __restrict__ feat,
            const float* __restrict__ W,
            const int*   __restrict__ nbr,
            float* __restrict__ out)
{
    __shared__ float featS[C_IN][TILE_N + 1];  // [32][129] ci-major
    __shared__ float wS[C_IN][C_OUT];          // 8KB
    __shared__ int   idxS[TILE_N];
    __shared__ float sSum[C_OUT];
    __shared__ float sSq[C_OUT];

    const int t    = threadIdx.x;
    const int base = blockIdx.x * TILE_N;
    const int tc   = t & 15;   // cout group: couts tc*4 .. tc*4+3
    const int tr   = t >> 4;   // 0..15, voxels tr + 16*j

    float acc[8][4];
#pragma unroll
    for (int j = 0; j < 8; j++)
#pragma unroll
        for (int u = 0; u < 4; u++) acc[j][u] = 0.f;

    if (t < C_OUT) { sSum[t] = 0.f; sSq[t] = 0.f; }

    for (int k = 0; k < NK; k++) {
        __syncthreads();  // previous compute done / sSum init visible

        // Stage neighbor indices for this offset
        if (t < TILE_N) {
            int v = base + t;
            idxS[t] = (v < N_VOX) ? nbr[k * N_VOX + v] : -1;
        }
        // Stage weight slice W[k][:][:] (2048 floats = 512 float4)
        {
            const float4* Wk = reinterpret_cast<const float4*>(W + (size_t)k * C_IN * C_OUT);
            float4* wS4 = reinterpret_cast<float4*>(&wS[0][0]);
            wS4[t]           = Wk[t];
            wS4[t + THREADS] = Wk[t + THREADS];
        }
        __syncthreads();

        // Gather: 128 voxels x 32 ci = 1024 float4 segments, 4 per thread
#pragma unroll
        for (int q = 0; q < 4; q++) {
            int lin  = t + THREADS * q;    // 0..1023
            int v    = lin >> 3;           // voxel within tile
            int part = lin & 7;            // which float4 of the 32-ci row
            int idx  = idxS[v];
            float4 val = make_float4(0.f, 0.f, 0.f, 0.f);
            if (idx >= 0)
                val = *reinterpret_cast<const float4*>(feat + (size_t)idx * C_IN + part * 4);
            featS[part * 4 + 0][v] = val.x;
            featS[part * 4 + 1][v] = val.y;
            featS[part * 4 + 2][v] = val.z;
            featS[part * 4 + 3][v] = val.w;
        }
        __syncthreads();

        // Microkernel: 32 ci x (8 voxels x 4 couts)
#pragma unroll
        for (int ci = 0; ci < C_IN; ci++) {
            float4 w = *reinterpret_cast<const float4*>(&wS[ci][tc * 4]);
#pragma unroll
            for (int j = 0; j < 8; j++) {
                float f = featS[ci][tr + 16 * j];
                acc[j][0] = fmaf(f, w.x, acc[j][0]);
                acc[j][1] = fmaf(f, w.y, acc[j][1]);
                acc[j][2] = fmaf(f, w.z, acc[j][2]);
                acc[j][3] = fmaf(f, w.w, acc[j][3]);
            }
        }
    }

    // Epilogue: write raw conv output + per-block channel sums
    float ls[4] = {0.f, 0.f, 0.f, 0.f};
    float lq[4] = {0.f, 0.f, 0.f, 0.f};
#pragma unroll
    for (int j = 0; j < 8; j++) {
        int v = base + tr + 16 * j;
        if (v < N_VOX) {
            float4 o = make_float4(acc[j][0], acc[j][1], acc[j][2], acc[j][3]);
            *reinterpret_cast<float4*>(out + (size_t)v * C_OUT + tc * 4) = o;
#pragma unroll
            for (int u = 0; u < 4; u++) {
                ls[u] += acc[j][u];
                lq[u] += acc[j][u] * acc[j][u];
            }
        }
    }
#pragma unroll
    for (int u = 0; u < 4; u++) {
        atomicAdd(&sSum[tc * 4 + u], ls[u]);
        atomicAdd(&sSq[tc * 4 + u], lq[u]);
    }
    __syncthreads();
    if (t < C_OUT) {
        atomicAdd(&g_sum[t], sSum[t]);
        atomicAdd(&g_sq[t],  sSq[t]);
    }
}

__global__ void stats_kernel(const float* __restrict__ gamma,
                             const float* __restrict__ beta)
{
    int c = threadIdx.x;
    if (c < C_OUT) {
        float mean = g_sum[c] / (float)N_VOX;
        float var  = g_sq[c] / (float)N_VOX - mean * mean;
        var = fmaxf(var, 0.f);
        float s = gamma[c] * rsqrtf(var + EPS);
        g_scale[c] = s;
        g_bias[c]  = beta[c] - mean * s;
    }
}

// Normalize + ReLU in place, vectorized float4. 64 couts = 16 float4 groups/row.
__global__ void apply_kernel(float* __restrict__ out)
{
    const int total4 = N_VOX * C_OUT / 4;
    for (int p = blockIdx.x * blockDim.x + threadIdx.x; p < total4;
         p += gridDim.x * blockDim.x) {
        int c4 = (p & 15) * 4;
        float4 x = reinterpret_cast<float4*>(out)[p];
        float4 s = *reinterpret_cast<const float4*>(&g_scale[c4]);
        float4 b = *reinterpret_cast<const float4*>(&g_bias[c4]);
        x.x = fmaxf(fmaf(x.x, s.x, b.x), 0.f);
        x.y = fmaxf(fmaf(x.y, s.y, b.y), 0.f);
        x.z = fmaxf(fmaf(x.z, s.z, b.z), 0.f);
        x.w = fmaxf(fmaf(x.w, s.w, b.w), 0.f);
        reinterpret_cast<float4*>(out)[p] = x;
    }
}

extern "C" void kernel_launch(void* const* d_in, const int* in_sizes, int n_in,
                              void* d_out, int out_size)
{
    const float* features = (const float*)d_in[0];   // [150000, 32]
    const float* weight   = (const float*)d_in[1];   // [27, 32, 64]
    const float* gamma    = (const float*)d_in[2];   // [64]
    const float* beta     = (const float*)d_in[3];   // [64]
    const int*   nbr      = (const int*)d_in[4];     // [27, 150000]
    float* out = (float*)d_out;                      // [150000, 64]

    zero_kernel<<<1, 64>>>();

    int grid = (N_VOX + TILE_N - 1) / TILE_N;        // 1172
    conv_kernel<<<grid, THREADS>>>(features, weight, nbr, out);

    stats_kernel<<<1, 64>>>(gamma, beta);

    apply_kernel<<<2048, 256>>>(out);
}

// round 5
// speedup vs baseline: 6.9808x; 6.9808x over previous
#include <cuda_runtime.h>
#include <cuda_bf16.h>

#define N_VOX 150000
#define C_IN  32
#define C_OUT 64
#define NK    27
#define EPS   1e-5f

#define TILE_N  128
#define THREADS 256
#define NE      (26 * N_VOX)   // extras entries (all offsets except center)

// Scratch for cross-kernel reduction (no cudaMalloc allowed).
__device__ float g_sum[C_OUT];
__device__ float g_sq[C_OUT];
__device__ float g_scale[C_OUT];
__device__ float g_bias[C_OUT];

__global__ void zero_kernel() {
    int t = threadIdx.x;
    if (t < C_OUT) { g_sum[t] = 0.f; g_sq[t] = 0.f; }
}

// ---------------------------------------------------------------------------
// K1: center-offset (k=13) gather + GEMM. This offset is always present.
// Block: 256 threads -> TILE_N=128 voxels x 64 couts, 8x4 register microtile.
// ---------------------------------------------------------------------------
__global__ void __launch_bounds__(THREADS, 2)
center_kernel(const float* __restrict__ feat,
              const float* __restrict__ W,
              const int*   __restrict__ nbr,
              float* __restrict__ out)
{
    __shared__ float featS[C_IN][TILE_N + 1];  // [32][129] ci-major
    __shared__ float wS[C_IN][C_OUT];          // 8KB (W[13])
    __shared__ int   idxS[TILE_N];

    const int t    = threadIdx.x;
    const int base = blockIdx.x * TILE_N;
    const int tc   = t & 15;   // cout group: couts tc*4 .. tc*4+3
    const int tr   = t >> 4;   // 0..15, voxels tr + 16*j

    // Stage neighbor indices for the center offset (k=13)
    if (t < TILE_N) {
        int v = base + t;
        idxS[t] = (v < N_VOX) ? nbr[13 * N_VOX + v] : -1;
    }
    // Stage weight slice W[13][:][:] (2048 floats = 512 float4)
    {
        const float4* Wk = reinterpret_cast<const float4*>(W + (size_t)13 * C_IN * C_OUT);
        float4* wS4 = reinterpret_cast<float4*>(&wS[0][0]);
        wS4[t]           = Wk[t];
        wS4[t + THREADS] = Wk[t + THREADS];
    }
    __syncthreads();

    // Gather: 128 voxels x 32 ci = 1024 float4 segments, 4 per thread
#pragma unroll
    for (int q = 0; q < 4; q++) {
        int lin  = t + THREADS * q;    // 0..1023
        int v    = lin >> 3;           // voxel within tile
        int part = lin & 7;            // which float4 of the 32-ci row
        int idx  = idxS[v];
        float4 val = make_float4(0.f, 0.f, 0.f, 0.f);
        if (idx >= 0)
            val = *reinterpret_cast<const float4*>(feat + (size_t)idx * C_IN + part * 4);
        featS[part * 4 + 0][v] = val.x;
        featS[part * 4 + 1][v] = val.y;
        featS[part * 4 + 2][v] = val.z;
        featS[part * 4 + 3][v] = val.w;
    }
    __syncthreads();

    float acc[8][4];
#pragma unroll
    for (int j = 0; j < 8; j++)
#pragma unroll
        for (int u = 0; u < 4; u++) acc[j][u] = 0.f;

    // Microkernel: 32 ci x (8 voxels x 4 couts)
#pragma unroll
    for (int ci = 0; ci < C_IN; ci++) {
        float4 w = *reinterpret_cast<const float4*>(&wS[ci][tc * 4]);
#pragma unroll
        for (int j = 0; j < 8; j++) {
            float f = featS[ci][tr + 16 * j];
            acc[j][0] = fmaf(f, w.x, acc[j][0]);
            acc[j][1] = fmaf(f, w.y, acc[j][1]);
            acc[j][2] = fmaf(f, w.z, acc[j][2]);
            acc[j][3] = fmaf(f, w.w, acc[j][3]);
        }
    }

    // Write center-only conv output (extras kernel accumulates on top)
#pragma unroll
    for (int j = 0; j < 8; j++) {
        int v = base + tr + 16 * j;
        if (v < N_VOX) {
            float4 o = make_float4(acc[j][0], acc[j][1], acc[j][2], acc[j][3]);
            *reinterpret_cast<float4*>(out + (size_t)v * C_OUT + tc * 4) = o;
        }
    }
}

// ---------------------------------------------------------------------------
// K2: sparse extras. Scan the 26 non-center rulebook rows; for each live
// (voxel, offset) pair the whole warp computes feat[idx] @ W[k] (32x64) and
// atomically accumulates into out. ~0.89% of entries are live.
// Lane l owns output channels (2l, 2l+1).
// ---------------------------------------------------------------------------
__global__ void __launch_bounds__(THREADS)
extras_kernel(const float* __restrict__ feat,
              const float* __restrict__ W,
              const int*   __restrict__ nbr,
              float* __restrict__ out)
{
    const int lane = threadIdx.x & 31;
    const long wg  = (long)((blockIdx.x * blockDim.x + threadIdx.x) >> 5);
    const long e   = wg * 32 + lane;

    int idx = -1, n = 0, k = 0;
    if (e < NE) {
        int kk = (int)(e / N_VOX);           // 0..25
        n  = (int)(e - (long)kk * N_VOX);
        k  = kk + (kk >= 13);                // skip center
        idx = nbr[(size_t)k * N_VOX + n];
    }

    unsigned bits = __ballot_sync(0xffffffffu, idx >= 0);
    const float2* W2 = reinterpret_cast<const float2*>(W);

    while (bits) {
        int b = __ffs(bits) - 1;
        bits &= bits - 1;
        int ib = __shfl_sync(0xffffffffu, idx, b);
        int nb = __shfl_sync(0xffffffffu, n,   b);
        int kb = __shfl_sync(0xffffffffu, k,   b);

        float f = feat[(size_t)ib * C_IN + lane];          // lane = ci
        const float2* Wk = W2 + (size_t)kb * C_IN * (C_OUT / 2);

        float ax = 0.f, ay = 0.f;
#pragma unroll
        for (int ci = 0; ci < C_IN; ci++) {
            float fv = __shfl_sync(0xffffffffu, f, ci);
            float2 w = __ldg(&Wk[ci * (C_OUT / 2) + lane]);
            ax = fmaf(fv, w.x, ax);
            ay = fmaf(fv, w.y, ay);
        }
        float* o = out + (size_t)nb * C_OUT + 2 * lane;
        atomicAdd(o,     ax);
        atomicAdd(o + 1, ay);
    }
}

// ---------------------------------------------------------------------------
// K3: per-channel sum / sumsq reduction over the finished conv output.
// Thread's channel quad is fixed because the grid stride is a multiple of 16.
// ---------------------------------------------------------------------------
__global__ void stats_reduce(const float* __restrict__ out)
{
    __shared__ float sS[C_OUT];
    __shared__ float sQ[C_OUT];
    const int t  = threadIdx.x;
    if (t < C_OUT) { sS[t] = 0.f; sQ[t] = 0.f; }
    __syncthreads();

    const int gt     = blockIdx.x * blockDim.x + t;
    const int stride = gridDim.x * blockDim.x;         // multiple of 16
    const int total4 = N_VOX * C_OUT / 4;              // 2,400,000
    const int c4     = (gt & 15) * 4;

    float4 s = make_float4(0.f, 0.f, 0.f, 0.f);
    float4 q = make_float4(0.f, 0.f, 0.f, 0.f);
    const float4* o4 = reinterpret_cast<const float4*>(out);
    for (int p = gt; p < total4; p += stride) {
        float4 x = o4[p];
        s.x += x.x; s.y += x.y; s.z += x.z; s.w += x.w;
        q.x += x.x * x.x; q.y += x.y * x.y; q.z += x.z * x.z; q.w += x.w * x.w;
    }
    atomicAdd(&sS[c4 + 0], s.x); atomicAdd(&sS[c4 + 1], s.y);
    atomicAdd(&sS[c4 + 2], s.z); atomicAdd(&sS[c4 + 3], s.w);
    atomicAdd(&sQ[c4 + 0], q.x); atomicAdd(&sQ[c4 + 1], q.y);
    atomicAdd(&sQ[c4 + 2], q.z); atomicAdd(&sQ[c4 + 3], q.w);
    __syncthreads();
    if (t < C_OUT) {
        atomicAdd(&g_sum[t], sS[t]);
        atomicAdd(&g_sq[t],  sQ[t]);
    }
}

__global__ void stats_final(const float* __restrict__ gamma,
                            const float* __restrict__ beta)
{
    int c = threadIdx.x;
    if (c < C_OUT) {
        float mean = g_sum[c] / (float)N_VOX;
        float var  = g_sq[c] / (float)N_VOX - mean * mean;
        var = fmaxf(var, 0.f);
        float s = gamma[c] * rsqrtf(var + EPS);
        g_scale[c] = s;
        g_bias[c]  = beta[c] - mean * s;
    }
}

// Normalize + ReLU in place, vectorized float4. 64 couts = 16 float4 groups/row.
__global__ void apply_kernel(float* __restrict__ out)
{
    const int total4 = N_VOX * C_OUT / 4;
    for (int p = blockIdx.x * blockDim.x + threadIdx.x; p < total4;
         p += gridDim.x * blockDim.x) {
        int c4 = (p & 15) * 4;
        float4 x = reinterpret_cast<float4*>(out)[p];
        float4 s = *reinterpret_cast<const float4*>(&g_scale[c4]);
        float4 b = *reinterpret_cast<const float4*>(&g_bias[c4]);
        x.x = fmaxf(fmaf(x.x, s.x, b.x), 0.f);
        x.y = fmaxf(fmaf(x.y, s.y, b.y), 0.f);
        x.z = fmaxf(fmaf(x.z, s.z, b.z), 0.f);
        x.w = fmaxf(fmaf(x.w, s.w, b.w), 0.f);
        reinterpret_cast<float4*>(out)[p] = x;
    }
}

extern "C" void kernel_launch(void* const* d_in, const int* in_sizes, int n_in,
                              void* d_out, int out_size)
{
    const float* features = (const float*)d_in[0];   // [150000, 32]
    const float* weight   = (const float*)d_in[1];   // [27, 32, 64]
    const float* gamma    = (const float*)d_in[2];   // [64]
    const float* beta     = (const float*)d_in[3];   // [64]
    const int*   nbr      = (const int*)d_in[4];     // [27, 150000]
    float* out = (float*)d_out;                      // [150000, 64]

    zero_kernel<<<1, 64>>>();

    int gridC = (N_VOX + TILE_N - 1) / TILE_N;       // 1172
    center_kernel<<<gridC, THREADS>>>(features, weight, nbr, out);

    int gridE = (NE + THREADS - 1) / THREADS;        // 15235 blocks (warp per 32 entries)
    extras_kernel<<<gridE, THREADS>>>(features, weight, nbr, out);

    stats_reduce<<<512, 256>>>(out);

    stats_final<<<1, 64>>>(gamma, beta);

    apply_kernel<<<2048, 256>>>(out);
}